// round 2
// baseline (speedup 1.0000x reference)
#include <cuda_runtime.h>
#include <cstdint>

// ---------------------------------------------------------------------------
// HybridSigLSTM: rolling signature + 2-layer LSTM(H=50) + MLP head + pd clip
// B=4096, S=256, DIN=4, WIN=5, D_AUG=5, SIG=30, COMB=35, GATES=4*50=200
// ---------------------------------------------------------------------------

#define B_TOT 4096
#define S_LEN 256
#define GATES 200
#define BT    28      // batch elements per CTA in recurrent kernel

typedef unsigned long long u64;

// scratch (device globals: allocation-free rule)
__device__ float g_xfeat[(size_t)B_TOT * S_LEN * 36];   // [b*S+t][36] padded sig feats
__device__ float g_pre0 [(size_t)B_TOT * S_LEN * 200];  // [t][b][o] transposed

// ---------------- helpers ----------------
__device__ __forceinline__ u64 ffma2(u64 a, u64 b, u64 c) {
    u64 d;
    asm("fma.rn.f32x2 %0, %1, %2, %3;" : "=l"(d) : "l"(a), "l"(b), "l"(c));
    return d;
}
__device__ __forceinline__ u64 pack2(float a, float b) {
    u64 r;
    asm("mov.b64 %0, {%1, %2};" : "=l"(r) : "f"(a), "f"(b));
    return r;
}
__device__ __forceinline__ float2 unpack2(u64 v) {
    float2 f;
    asm("mov.b64 {%0, %1}, %2;" : "=f"(f.x), "=f"(f.y) : "l"(v));
    return f;
}
__device__ __forceinline__ float ex2f(float x) {
    float y; asm("ex2.approx.f32 %0, %1;" : "=f"(y) : "f"(x)); return y;
}
__device__ __forceinline__ float rcpf(float x) {
    float y; asm("rcp.approx.f32 %0, %1;" : "=f"(y) : "f"(x)); return y;
}
// sigmoid(x) = 1/(1+2^(-x*log2(e)))
__device__ __forceinline__ float sigf(float x) {
    return rcpf(1.0f + ex2f(-1.4426950408889634f * x));
}
// tanh(x) = 2*sigmoid(2x)-1
__device__ __forceinline__ float tanha(float x) {
    return 2.0f * rcpf(1.0f + ex2f(-2.8853900817779268f * x)) - 1.0f;
}

// ---------------------------------------------------------------------------
// K1: rolling signature features -> g_xfeat[b*S+t][0:36]
//     x[0:4]=feat, x[4:9]=lvl1, x[9:34]=lvl2(i*5+j), x[34:36]=0 (pad)
// ---------------------------------------------------------------------------
__global__ __launch_bounds__(256) void sig_kernel(const float* __restrict__ features) {
    int gid = blockIdx.x * 256 + threadIdx.x;      // gid = b*S + t
    int b = gid >> 8;
    int t = gid & 255;
    const float4* f4 = (const float4*)features + (size_t)b * S_LEN;

    float a[5][5];   // window of time-augmented path [k][dim]
#pragma unroll
    for (int k = 0; k < 5; k++) {
        int idx = t + k - 4; if (idx < 0) idx = 0;
        float4 fv = __ldg(&f4[idx]);
        a[k][0] = (float)idx * (1.0f / 255.0f);
        a[k][1] = fv.x; a[k][2] = fv.y; a[k][3] = fv.z; a[k][4] = fv.w;
    }
    float x[36];
    x[0] = a[4][1]; x[1] = a[4][2]; x[2] = a[4][3]; x[3] = a[4][4];
#pragma unroll
    for (int i = 0; i < 5; i++) x[4 + i] = a[4][i] - a[0][i];
#pragma unroll
    for (int i = 0; i < 5; i++) {
#pragma unroll
        for (int j = 0; j < 5; j++) {
            float s = 0.0f;
#pragma unroll
            for (int k = 0; k < 4; k++) s += (a[k + 1][i] - a[k][i]) * a[k][j];
            x[9 + i * 5 + j] = s;
        }
    }
    x[34] = 0.0f; x[35] = 0.0f;

    float4* dst = (float4*)(g_xfeat + (size_t)gid * 36);
#pragma unroll
    for (int q = 0; q < 9; q++)
        dst[q] = make_float4(x[4 * q], x[4 * q + 1], x[4 * q + 2], x[4 * q + 3]);
}

// ---------------------------------------------------------------------------
// K2: pre0[t][b][o] = b_ih0[o]+b_hh0[o] + sum_{k<34} W_ih0[o][k]*x[b,t,k]
//     (column 34 of W_ih0 multiplies pd; handled in recurrent kernel)
// ---------------------------------------------------------------------------
__global__ __launch_bounds__(256) void pre0_kernel(const float* __restrict__ w_ih0,
                                                   const float* __restrict__ b_ih0,
                                                   const float* __restrict__ b_hh0) {
    __shared__ __align__(16) float xs[64][36];
    int tid = threadIdx.x;
    size_t row0 = (size_t)blockIdx.x * 64;

    u64 wp[17];
    float bias = 0.0f;
    if (tid < GATES) {
        const float* wr = w_ih0 + tid * 35;   // row stride COMB=35
#pragma unroll
        for (int j = 0; j < 17; j++) wp[j] = pack2(wr[2 * j], wr[2 * j + 1]);
        bias = b_ih0[tid] + b_hh0[tid];
    }
    const float* src = g_xfeat + row0 * 36;
#pragma unroll
    for (int n = 0; n < 9; n++) ((float*)xs)[tid + n * 256] = src[tid + n * 256];
    __syncthreads();

    if (tid < GATES) {
        for (int r = 0; r < 64; r += 2) {
            const ulonglong2* xA = (const ulonglong2*)&xs[r][0];
            const ulonglong2* xB = (const ulonglong2*)&xs[r + 1][0];
            u64 aA = 0ull, aB = 0ull;
#pragma unroll
            for (int q = 0; q < 8; q++) {
                ulonglong2 vA = xA[q], vB = xB[q];
                aA = ffma2(wp[2 * q],     vA.x, aA);
                aB = ffma2(wp[2 * q],     vB.x, aB);
                aA = ffma2(wp[2 * q + 1], vA.y, aA);
                aB = ffma2(wp[2 * q + 1], vB.y, aB);
            }
            u64 tA = ((const u64*)&xs[r][0])[16];       // floats 32,33
            u64 tB = ((const u64*)&xs[r + 1][0])[16];
            aA = ffma2(wp[16], tA, aA);
            aB = ffma2(wp[16], tB, aB);
            float2 fA = unpack2(aA), fB = unpack2(aB);
            size_t ra = row0 + r, rb = row0 + r + 1;    // row = b*S + t
            size_t ia = ((ra & 255) * (size_t)B_TOT + (ra >> 8)) * 200 + tid;
            size_t ib = ((rb & 255) * (size_t)B_TOT + (rb >> 8)) * 200 + tid;
            g_pre0[ia] = fA.x + fA.y + bias;
            g_pre0[ib] = fB.x + fB.y + bias;
        }
    }
}

// ---------------------------------------------------------------------------
// K3: recurrent kernel. One CTA = BT batch elements, 256 steps.
// ---------------------------------------------------------------------------
__global__ __launch_bounds__(256, 1) void rec_kernel(
    const float* __restrict__ w_ih0, const float* __restrict__ w_hh0,
    const float* __restrict__ w_ih1, const float* __restrict__ w_hh1,
    const float* __restrict__ b_ih1, const float* __restrict__ b_hh1,
    const float* __restrict__ w1,    const float* __restrict__ b1,
    const float* __restrict__ w2,    const float* __restrict__ b2,
    float* __restrict__ out)
{
    __shared__ __align__(16) float h0s[BT][52];
    __shared__ __align__(16) float h1s[BT][52];
    __shared__ __align__(16) float z_s[BT][200];
    __shared__ __align__(16) float w1s[25][52];
    __shared__ float hd[BT][25];
    __shared__ float pd_s[BT];
    __shared__ float b1s[25], w2s[25];
    __shared__ float b2s;

    const int tid = threadIdx.x;
    const int o   = tid;
    const int b0  = blockIdx.x * BT;
    int bt = B_TOT - b0; if (bt > BT) bt = BT;   // 28 or 8 (always even)

    // --- per-thread weight rows, packed f32x2 ---
    u64 w0p[25], wi1p[25], wh1p[25];
    float wpd = 0.0f, bias1 = 0.0f;
    if (o < GATES) {
        const float* r0 = w_hh0 + o * 50;
#pragma unroll
        for (int j = 0; j < 25; j++) w0p[j]  = pack2(r0[2 * j], r0[2 * j + 1]);
        const float* r1 = w_ih1 + o * 50;
#pragma unroll
        for (int j = 0; j < 25; j++) wi1p[j] = pack2(r1[2 * j], r1[2 * j + 1]);
        const float* r2 = w_hh1 + o * 50;
#pragma unroll
        for (int j = 0; j < 25; j++) wh1p[j] = pack2(r2[2 * j], r2[2 * j + 1]);
        wpd   = w_ih0[o * 35 + 34];
        bias1 = b_ih1[o] + b_hh1[o];
    }

    // --- init state / head weights ---
    for (int i = tid; i < BT * 52; i += 256) { ((float*)h0s)[i] = 0.0f; ((float*)h1s)[i] = 0.0f; }
    for (int i = tid; i < 1250; i += 256) { int j = i / 50, k = i - j * 50; w1s[j][k] = w1[i]; }
    if (tid < 25) { b1s[tid] = b1[tid]; w2s[tid] = w2[tid]; }
    if (tid < BT) pd_s[tid] = 0.0f;
    if (tid == 0) b2s = b2[0];
    float c0r[6], c1r[6];
#pragma unroll
    for (int n = 0; n < 6; n++) { c0r[n] = 0.0f; c1r[n] = 0.0f; }
    __syncthreads();

    const int nact = bt * 50;
    const int nhd  = bt * 25;
    const int nz4  = bt * 50;   // float4 count of pre0 tile

    for (int t = 0; t < S_LEN; t++) {
        // --- stage pre0 tile into z_s (coalesced float4) ---
        {
            const float4* psrc = (const float4*)(g_pre0 + ((size_t)t * B_TOT + b0) * 200);
            float4* zdst = (float4*)&z_s[0][0];
#pragma unroll
            for (int n = 0; n < 6; n++) {
                int idx = tid + n * 256;
                if (idx < nz4) zdst[idx] = psrc[idx];
            }
        }
        __syncthreads();

        // --- Z0: z += W_hh0[o,:]·h0[b,:] + wpd*pd[b] ---
        if (o < GATES) {
            for (int b = 0; b < bt; b += 2) {
                const ulonglong2* hA = (const ulonglong2*)&h0s[b][0];
                const ulonglong2* hB = (const ulonglong2*)&h0s[b + 1][0];
                u64 aA = 0ull, aB = 0ull;
#pragma unroll
                for (int q = 0; q < 12; q++) {
                    ulonglong2 vA = hA[q], vB = hB[q];
                    aA = ffma2(w0p[2 * q],     vA.x, aA);
                    aB = ffma2(w0p[2 * q],     vB.x, aB);
                    aA = ffma2(w0p[2 * q + 1], vA.y, aA);
                    aB = ffma2(w0p[2 * q + 1], vB.y, aB);
                }
                u64 tA = ((const u64*)&h0s[b][0])[24];      // floats 48,49
                u64 tB = ((const u64*)&h0s[b + 1][0])[24];
                aA = ffma2(w0p[24], tA, aA);
                aB = ffma2(w0p[24], tB, aB);
                float2 fA = unpack2(aA), fB = unpack2(aB);
                z_s[b][o]     += fA.x + fA.y + wpd * pd_s[b];
                z_s[b + 1][o] += fB.x + fB.y + wpd * pd_s[b + 1];
            }
        }
        __syncthreads();

        // --- act0: LSTM cell layer 0 ---
#pragma unroll
        for (int n = 0; n < 6; n++) {
            int idx = tid + n * 256;
            if (idx < nact) {
                int b = idx / 50, u = idx - b * 50;
                float iv = z_s[b][u], fv = z_s[b][u + 50];
                float gv = z_s[b][u + 100], ov = z_s[b][u + 150];
                float c = sigf(fv) * c0r[n] + sigf(iv) * tanha(gv);
                c0r[n] = c;
                h0s[b][u] = sigf(ov) * tanha(c);
            }
        }
        __syncthreads();

        // --- Z1: z = bias1 + W_ih1[o,:]·h0new[b,:] + W_hh1[o,:]·h1[b,:] ---
        if (o < GATES) {
            for (int b = 0; b < bt; b += 2) {
                const ulonglong2* hA0 = (const ulonglong2*)&h0s[b][0];
                const ulonglong2* hB0 = (const ulonglong2*)&h0s[b + 1][0];
                const ulonglong2* hA1 = (const ulonglong2*)&h1s[b][0];
                const ulonglong2* hB1 = (const ulonglong2*)&h1s[b + 1][0];
                u64 aA = 0ull, aB = 0ull;
#pragma unroll
                for (int q = 0; q < 12; q++) {
                    ulonglong2 vA0 = hA0[q], vB0 = hB0[q];
                    ulonglong2 vA1 = hA1[q], vB1 = hB1[q];
                    aA = ffma2(wi1p[2 * q],     vA0.x, aA);
                    aB = ffma2(wi1p[2 * q],     vB0.x, aB);
                    aA = ffma2(wi1p[2 * q + 1], vA0.y, aA);
                    aB = ffma2(wi1p[2 * q + 1], vB0.y, aB);
                    aA = ffma2(wh1p[2 * q],     vA1.x, aA);
                    aB = ffma2(wh1p[2 * q],     vB1.x, aB);
                    aA = ffma2(wh1p[2 * q + 1], vA1.y, aA);
                    aB = ffma2(wh1p[2 * q + 1], vB1.y, aB);
                }
                u64 tA0 = ((const u64*)&h0s[b][0])[24];
                u64 tB0 = ((const u64*)&h0s[b + 1][0])[24];
                u64 tA1 = ((const u64*)&h1s[b][0])[24];
                u64 tB1 = ((const u64*)&h1s[b + 1][0])[24];
                aA = ffma2(wi1p[24], tA0, aA);
                aB = ffma2(wi1p[24], tB0, aB);
                aA = ffma2(wh1p[24], tA1, aA);
                aB = ffma2(wh1p[24], tB1, aB);
                float2 fA = unpack2(aA), fB = unpack2(aB);
                z_s[b][o]     = bias1 + fA.x + fA.y;
                z_s[b + 1][o] = bias1 + fB.x + fB.y;
            }
        }
        __syncthreads();

        // --- act1: LSTM cell layer 1 ---
#pragma unroll
        for (int n = 0; n < 6; n++) {
            int idx = tid + n * 256;
            if (idx < nact) {
                int b = idx / 50, u = idx - b * 50;
                float iv = z_s[b][u], fv = z_s[b][u + 50];
                float gv = z_s[b][u + 100], ov = z_s[b][u + 150];
                float c = sigf(fv) * c1r[n] + sigf(iv) * tanha(gv);
                c1r[n] = c;
                h1s[b][u] = sigf(ov) * tanha(c);
            }
        }
        __syncthreads();

        // --- head layer 1: hd = relu(W1·h1 + b1) ---
#pragma unroll
        for (int n = 0; n < 3; n++) {
            int idx = tid + n * 256;
            if (idx < nhd) {
                int b = idx / 25, j = idx - b * 25;
                float s = b1s[j];
#pragma unroll
                for (int u = 0; u < 50; u++) s += w1s[j][u] * h1s[b][u];
                hd[b][j] = fmaxf(s, 0.0f);
            }
        }
        __syncthreads();

        // --- head layer 2 + pd update ---
        if (tid < bt) {
            float s = b2s;
#pragma unroll
            for (int j = 0; j < 25; j++) s += w2s[j] * hd[tid][j];
            float nd = pd_s[tid] + 0.2f * tanha(s);
            nd = fminf(fmaxf(nd, -1.5f), 1.5f);
            pd_s[tid] = nd;
            out[(size_t)(b0 + tid) * S_LEN + t] = nd;
        }
        __syncthreads();
    }
}

// ---------------------------------------------------------------------------
extern "C" void kernel_launch(void* const* d_in, const int* in_sizes, int n_in,
                              void* d_out, int out_size) {
    const float* features = (const float*)d_in[0];
    const float* w_ih0    = (const float*)d_in[1];
    const float* w_hh0    = (const float*)d_in[2];
    const float* b_ih0    = (const float*)d_in[3];
    const float* b_hh0    = (const float*)d_in[4];
    const float* w_ih1    = (const float*)d_in[5];
    const float* w_hh1    = (const float*)d_in[6];
    const float* b_ih1    = (const float*)d_in[7];
    const float* b_hh1    = (const float*)d_in[8];
    const float* w1       = (const float*)d_in[9];
    const float* b1       = (const float*)d_in[10];
    const float* w2       = (const float*)d_in[11];
    const float* b2       = (const float*)d_in[12];
    float* out = (float*)d_out;

    sig_kernel<<<(B_TOT * S_LEN) / 256, 256>>>(features);
    pre0_kernel<<<(B_TOT * S_LEN) / 64, 256>>>(w_ih0, b_ih0, b_hh0);
    rec_kernel<<<(B_TOT + BT - 1) / BT, 256>>>(w_ih0, w_hh0, w_ih1, w_hh1,
                                               b_ih1, b_hh1, w1, b1, w2, b2, out);
}